// round 1
// baseline (speedup 1.0000x reference)
#include <cuda_runtime.h>
#include <cuda_bf16.h>
#include <math.h>

#define N_SAMP 1024
#define N_FEAT 512
#define N_LAB  16

#define THRESH   0.5f
#define MARGIN   0.1f
#define SCALE_P  0.05f
#define SCALE_N  0.002f
#define ONE_EPS  0.99999f   // 1.0 - 1e-5

// ---- scratch (no allocations allowed) ----
__device__ float    g_sim[N_SAMP * N_SAMP];        // 4 MB, L2-resident
__device__ unsigned g_posmask[N_LAB][N_SAMP / 32]; // bit j: labels[j][c]==1
__device__ int      g_total;                       // total anchors
__device__ float    g_rowloss[N_SAMP];

// ============================================================
// Kernel A: label bitmasks + anchor count.  <<<1, 512>>>
// ============================================================
__global__ void prep_kernel(const int* __restrict__ labels) {
    int t = threadIdx.x;          // 0..511
    int c = t >> 5;               // 0..15
    int w = t & 31;               // word index 0..31
    int base = w * 32;
    unsigned m = 0;
#pragma unroll
    for (int b = 0; b < 32; b++) {
        if (labels[(base + b) * N_LAB + c] == 1) m |= (1u << b);
    }
    g_posmask[c][w] = m;

    int cnt = __popc(m);
#pragma unroll
    for (int o = 16; o; o >>= 1) cnt += __shfl_down_sync(0xffffffffu, cnt, o);
    __shared__ int red[16];
    if ((t & 31) == 0) red[t >> 5] = cnt;
    __syncthreads();
    if (t == 0) {
        int v = 0;
#pragma unroll
        for (int k = 0; k < 16; k++) v += red[k];
        g_total = v;
    }
}

// ============================================================
// Kernel B: sim = F @ F^T  (1024x1024x512 fp32 SGEMM)
// 128x128 block tile, 16 K-tile, 8x8 per thread, 256 threads.
// ============================================================
__global__ void __launch_bounds__(256) sgemm_kernel(const float* __restrict__ F) {
    __shared__ float As[16][128];
    __shared__ float Bs[16][128];

    const int tid = threadIdx.x;
    const int bm = blockIdx.y * 128;
    const int bn = blockIdx.x * 128;
    const int tm = (tid / 16) * 8;
    const int tn = (tid % 16) * 8;
    const int r0 = tid >> 2;            // 0..63
    const int kq = (tid & 3) * 4;       // 0,4,8,12

    float acc[8][8];
#pragma unroll
    for (int r = 0; r < 8; r++)
#pragma unroll
        for (int c = 0; c < 8; c++) acc[r][c] = 0.f;

    for (int k0 = 0; k0 < N_FEAT; k0 += 16) {
#pragma unroll
        for (int l = 0; l < 2; l++) {
            int row = r0 + l * 64;
            float4 va = *(const float4*)(F + (size_t)(bm + row) * N_FEAT + k0 + kq);
            As[kq + 0][row] = va.x; As[kq + 1][row] = va.y;
            As[kq + 2][row] = va.z; As[kq + 3][row] = va.w;
            float4 vb = *(const float4*)(F + (size_t)(bn + row) * N_FEAT + k0 + kq);
            Bs[kq + 0][row] = vb.x; Bs[kq + 1][row] = vb.y;
            Bs[kq + 2][row] = vb.z; Bs[kq + 3][row] = vb.w;
        }
        __syncthreads();
#pragma unroll
        for (int kk = 0; kk < 16; kk++) {
            float a[8], b[8];
            *(float4*)(a)     = *(const float4*)&As[kk][tm];
            *(float4*)(a + 4) = *(const float4*)&As[kk][tm + 4];
            *(float4*)(b)     = *(const float4*)&Bs[kk][tn];
            *(float4*)(b + 4) = *(const float4*)&Bs[kk][tn + 4];
#pragma unroll
            for (int r = 0; r < 8; r++)
#pragma unroll
                for (int c = 0; c < 8; c++)
                    acc[r][c] = fmaf(a[r], b[c], acc[r][c]);
        }
        __syncthreads();
    }

#pragma unroll
    for (int r = 0; r < 8; r++) {
        float* cp = g_sim + (size_t)(bm + tm + r) * N_SAMP + bn + tn;
        *(float4*)(cp)     = make_float4(acc[r][0], acc[r][1], acc[r][2], acc[r][3]);
        *(float4*)(cp + 4) = make_float4(acc[r][4], acc[r][5], acc[r][6], acc[r][7]);
    }
}

// ============================================================
// Kernel C: per-anchor-row loss.  <<<1024, 512>>>
// One block per anchor row i; warp w handles label column c = w.
// ============================================================
__global__ void __launch_bounds__(512) loss_kernel() {
    const int i = blockIdx.x;
    const int t = threadIdx.x;

    __shared__ float s_sh[N_SAMP];
    __shared__ float ep_sh[N_SAMP];
    __shared__ float en_sh[N_SAMP];
    __shared__ float warpres[16];

    const float* row = g_sim + (size_t)i * N_SAMP;
#pragma unroll
    for (int j = t; j < N_SAMP; j += 512) {
        float sv = row[j];
        s_sh[j] = sv;
        float d = sv - THRESH;
        ep_sh[j] = __expf(-SCALE_P * d);
        en_sh[j] = __expf(SCALE_N * d);
    }
    __syncthreads();

    const int w = t >> 5;       // warp = label column c
    const int lane = t & 31;
    const int c = w;

    float contrib = 0.f;
    unsigned anchorw = g_posmask[c][i >> 5];
    bool anchor = (anchorw >> (i & 31)) & 1u;

    if (anchor) {
        unsigned myword = g_posmask[c][lane];  // word 'lane' of column c

        // -------- pass 1: min_pos (filtered), max_neg --------
        float minp = 1e30f, maxn = -1e30f;
#pragma unroll
        for (int it = 0; it < 32; it++) {
            unsigned m = __shfl_sync(0xffffffffu, myword, it);
            float sv = s_sh[it * 32 + lane];
            if ((m >> lane) & 1u) {
                if (sv < ONE_EPS) minp = fminf(minp, sv);
            } else {
                maxn = fmaxf(maxn, sv);
            }
        }
#pragma unroll
        for (int o = 16; o; o >>= 1) {
            minp = fminf(minp, __shfl_xor_sync(0xffffffffu, minp, o));
            maxn = fmaxf(maxn, __shfl_xor_sync(0xffffffffu, maxn, o));
        }
        float minp_eff = (minp < 1e29f) ? minp : -1e30f;

        // -------- pass 2: selected exp-sums --------
        float ps = 0.f, ns = 0.f;
        bool psel = false, nsel = false;
#pragma unroll
        for (int it = 0; it < 32; it++) {
            unsigned m = __shfl_sync(0xffffffffu, myword, it);
            int j = it * 32 + lane;
            float sv = s_sh[j];
            if ((m >> lane) & 1u) {
                if (sv < ONE_EPS && sv - MARGIN < maxn) { ps += ep_sh[j]; psel = true; }
            } else {
                if (sv + MARGIN > minp_eff) { ns += en_sh[j]; nsel = true; }
            }
        }
#pragma unroll
        for (int o = 16; o; o >>= 1) {
            ps += __shfl_xor_sync(0xffffffffu, ps, o);
            ns += __shfl_xor_sync(0xffffffffu, ns, o);
        }
        bool anyp = __any_sync(0xffffffffu, psel);
        bool anyn = __any_sync(0xffffffffu, nsel);
        if (anyp && anyn)
            contrib = log1pf(ps) / SCALE_P + log1pf(ns) / SCALE_N;
    }

    if (lane == 0) warpres[w] = contrib;
    __syncthreads();
    if (t == 0) {
        float sum = 0.f;
#pragma unroll
        for (int k = 0; k < 16; k++) sum += warpres[k];
        g_rowloss[i] = sum;
    }
}

// ============================================================
// Kernel D: final deterministic reduction.  <<<1, 256>>>
// ============================================================
__global__ void final_kernel(float* __restrict__ out) {
    int t = threadIdx.x;
    float sum = 0.f;
#pragma unroll
    for (int j = t; j < N_SAMP; j += 256) sum += g_rowloss[j];
#pragma unroll
    for (int o = 16; o; o >>= 1) sum += __shfl_xor_sync(0xffffffffu, sum, o);
    __shared__ float red[8];
    if ((t & 31) == 0) red[t >> 5] = sum;
    __syncthreads();
    if (t == 0) {
        float tot = 0.f;
#pragma unroll
        for (int k = 0; k < 8; k++) tot += red[k];
        int ta = g_total;
        out[0] = (ta > 0) ? tot / (float)ta : 0.f;
    }
}

// ============================================================
extern "C" void kernel_launch(void* const* d_in, const int* in_sizes, int n_in,
                              void* d_out, int out_size) {
    const float* feats = (const float*)d_in[0];   // (1024, 512) f32
    const int* labels  = (const int*)d_in[1];     // (1024, 16) i32
    float* out = (float*)d_out;

    prep_kernel<<<1, 512>>>(labels);
    sgemm_kernel<<<dim3(8, 8), 256>>>(feats);
    loss_kernel<<<N_SAMP, 512>>>();
    final_kernel<<<1, 256>>>(out);
}

// round 3
// speedup vs baseline: 1.4409x; 1.4409x over previous
#include <cuda_runtime.h>
#include <cuda_bf16.h>
#include <math.h>
#include <cstdint>

#define N_SAMP 1024
#define N_FEAT 512
#define N_LAB  16

#define THRESH   0.5f
#define MARGIN   0.1f
#define SCALE_P  0.05f
#define SCALE_N  0.002f
#define ONE_EPS  0.99999f   // 1.0 - 1e-5

// ---- scratch (no allocations allowed) ----
__device__ float          g_sim[N_SAMP * N_SAMP];        // 4 MB, L2-resident
__device__ __nv_bfloat16  g_hi[N_SAMP * N_FEAT];         // 1 MB
__device__ __nv_bfloat16  g_lo[N_SAMP * N_FEAT];         // 1 MB
__device__ unsigned       g_posmask[N_LAB][N_SAMP / 32];
__device__ int            g_total;
__device__ float          g_rowloss[N_SAMP];

// ============================================================
// PTX helpers (baseline ISA only: cp.async / ldmatrix / mma.sync)
// ============================================================
__device__ __forceinline__ uint32_t smem_u32(const void* p) {
    uint32_t a;
    asm("{ .reg .u64 t; cvta.to.shared.u64 t, %1; cvt.u32.u64 %0, t; }" : "=r"(a) : "l"(p));
    return a;
}
#define CP_ASYNC16(s, g) asm volatile("cp.async.cg.shared.global [%0], [%1], 16;" :: "r"(s), "l"(g) : "memory")
#define CP_COMMIT()      asm volatile("cp.async.commit_group;" ::: "memory")
#define CP_WAIT1()       asm volatile("cp.async.wait_group 1;" ::: "memory")
#define CP_WAIT0()       asm volatile("cp.async.wait_group 0;" ::: "memory")

__device__ __forceinline__ void ldmatrix4(uint32_t* r, uint32_t addr) {
    asm volatile("ldmatrix.sync.aligned.m8n8.x4.shared.b16 {%0,%1,%2,%3}, [%4];"
        : "=r"(r[0]), "=r"(r[1]), "=r"(r[2]), "=r"(r[3]) : "r"(addr));
}
__device__ __forceinline__ void mma16816(float* d, const uint32_t* a, const uint32_t* b) {
    asm volatile("mma.sync.aligned.m16n8k16.row.col.f32.bf16.bf16.f32 "
        "{%0,%1,%2,%3}, {%4,%5,%6,%7}, {%8,%9}, {%0,%1,%2,%3};"
        : "+f"(d[0]), "+f"(d[1]), "+f"(d[2]), "+f"(d[3])
        : "r"(a[0]), "r"(a[1]), "r"(a[2]), "r"(a[3]), "r"(b[0]), "r"(b[1]));
}
#define SW128(off) ((off) ^ (((off) >> 3) & 0x70))

// ============================================================
// Kernel A: label bitmasks + anchor count.  <<<1, 512>>>
// ============================================================
__global__ void prep_kernel(const int* __restrict__ labels) {
    int t = threadIdx.x;
    int c = t >> 5;
    int w = t & 31;
    int base = w * 32;
    unsigned m = 0;
#pragma unroll
    for (int b = 0; b < 32; b++) {
        if (labels[(base + b) * N_LAB + c] == 1) m |= (1u << b);
    }
    g_posmask[c][w] = m;

    int cnt = __popc(m);
#pragma unroll
    for (int o = 16; o; o >>= 1) cnt += __shfl_down_sync(0xffffffffu, cnt, o);
    __shared__ int red[16];
    if ((t & 31) == 0) red[t >> 5] = cnt;
    __syncthreads();
    if (t == 0) {
        int v = 0;
#pragma unroll
        for (int k = 0; k < 16; k++) v += red[k];
        g_total = v;
    }
}

// ============================================================
// Kernel B1: fp32 -> (bf16 hi, bf16 lo) split.  <<<512, 256>>>
// ============================================================
__global__ void __launch_bounds__(256) conv_kernel(const float* __restrict__ F) {
    int gid = blockIdx.x * 256 + threadIdx.x;   // 131072 float4 groups
    float4 v = ((const float4*)F)[gid];
    __nv_bfloat16 hx = __float2bfloat16(v.x);
    __nv_bfloat16 hy = __float2bfloat16(v.y);
    __nv_bfloat16 hz = __float2bfloat16(v.z);
    __nv_bfloat16 hw = __float2bfloat16(v.w);
    __nv_bfloat16 lx = __float2bfloat16(v.x - __bfloat162float(hx));
    __nv_bfloat16 ly = __float2bfloat16(v.y - __bfloat162float(hy));
    __nv_bfloat16 lz = __float2bfloat16(v.z - __bfloat162float(hz));
    __nv_bfloat16 lw = __float2bfloat16(v.w - __bfloat162float(hw));
    __nv_bfloat162* ho = (__nv_bfloat162*)g_hi;
    __nv_bfloat162* lo = (__nv_bfloat162*)g_lo;
    ho[gid * 2 + 0] = __nv_bfloat162(hx, hy);
    ho[gid * 2 + 1] = __nv_bfloat162(hz, hw);
    lo[gid * 2 + 0] = __nv_bfloat162(lx, ly);
    lo[gid * 2 + 1] = __nv_bfloat162(lz, lw);
}

// ============================================================
// Kernel B2: sim = hi@hi^T + hi@lo^T + lo@hi^T via mma.sync bf16.
// CTA tile 128x128, 8 warps (2x4), warp tile 64x32, K-chunk 64,
// cp.async double-buffered, SW128-swizzled smem.
// ============================================================
#define STAGE_BYTES 32768           // 16KB A + 16KB B
#define SM_MMA_TOTAL (2 * STAGE_BYTES)

struct MmaCtx {
    uint32_t sb;
    int tid, bm, bn;
};

__device__ __forceinline__ void issue_chunk(const MmaCtx& cx, int chunk, int stage) {
    const int p  = chunk >> 3;
    const int kc = (chunk & 7) * 64;
    const __nv_bfloat16* Asrc = (p == 2) ? g_lo : g_hi;
    const __nv_bfloat16* Bsrc = (p == 1) ? g_lo : g_hi;
    const int row  = cx.tid >> 1;
    const int half = cx.tid & 1;
    const char* gA = (const char*)(Asrc + (size_t)(cx.bm + row) * N_FEAT + kc) + half * 64;
    const char* gB = (const char*)(Bsrc + (size_t)(cx.bn + row) * N_FEAT + kc) + half * 64;
    uint32_t sA = cx.sb + stage * STAGE_BYTES;
    uint32_t sB = sA + 16384;
#pragma unroll
    for (int j = 0; j < 4; j++) {
        uint32_t off = SW128((uint32_t)(row * 128 + half * 64 + j * 16));
        CP_ASYNC16(sA + off, gA + j * 16);
        CP_ASYNC16(sB + off, gB + j * 16);
    }
    CP_COMMIT();
}

__global__ void __launch_bounds__(256) mma_kernel() {
    extern __shared__ char smem[];
    MmaCtx cx;
    cx.sb  = smem_u32(smem);
    cx.tid = threadIdx.x;
    cx.bm  = blockIdx.y * 128;
    cx.bn  = blockIdx.x * 128;

    const int wid  = cx.tid >> 5;
    const int lane = cx.tid & 31;
    const int wm   = (wid & 1) * 64;   // warp M offset in tile
    const int wn   = (wid >> 1) * 32;  // warp N offset in tile

    float acc[4][4][4];
#pragma unroll
    for (int mt = 0; mt < 4; mt++)
#pragma unroll
        for (int nt = 0; nt < 4; nt++)
#pragma unroll
            for (int q = 0; q < 4; q++) acc[mt][nt][q] = 0.f;

    issue_chunk(cx, 0, 0);
    issue_chunk(cx, 1, 1);

    // precompute swizzled ldmatrix offsets (row part varies by kk only in k-bytes)
    const int a_row = wm + (lane & 15);
    const int a_kb  = (lane >> 4) * 16;
    const int b_row = wn + ((lane >> 4) << 3) + (lane & 7);
    const int b_kb  = ((lane >> 3) & 1) << 4;

    for (int it = 0; it < 24; it++) {
        if (it < 22) { CP_WAIT1(); } else { CP_WAIT0(); }
        __syncthreads();
        uint32_t aBase = cx.sb + (it & 1) * STAGE_BYTES;
        uint32_t bBase = aBase + 16384;

#pragma unroll
        for (int kk = 0; kk < 4; kk++) {
            uint32_t a[4][4], b[2][4];
#pragma unroll
            for (int mt = 0; mt < 4; mt++) {
                uint32_t off = SW128((uint32_t)((a_row + mt * 16) * 128 + kk * 32 + a_kb));
                ldmatrix4(a[mt], aBase + off);
            }
#pragma unroll
            for (int nt2 = 0; nt2 < 2; nt2++) {
                uint32_t off = SW128((uint32_t)((b_row + nt2 * 16) * 128 + kk * 32 + b_kb));
                ldmatrix4(b[nt2], bBase + off);
            }
#pragma unroll
            for (int mt = 0; mt < 4; mt++)
#pragma unroll
                for (int nt = 0; nt < 4; nt++)
                    mma16816(acc[mt][nt], a[mt], &b[nt >> 1][(nt & 1) * 2]);
        }
        __syncthreads();
        if (it + 2 < 24) issue_chunk(cx, it + 2, it & 1);
    }

    // epilogue: write accumulators to g_sim
    const int r0 = cx.bm + wm + (lane >> 2);
    const int c0 = cx.bn + wn + (lane & 3) * 2;
#pragma unroll
    for (int mt = 0; mt < 4; mt++)
#pragma unroll
        for (int nt = 0; nt < 4; nt++) {
            float* p0 = g_sim + (size_t)(r0 + mt * 16) * N_SAMP + c0 + nt * 8;
            *(float2*)p0 = make_float2(acc[mt][nt][0], acc[mt][nt][1]);
            *(float2*)(p0 + 8 * N_SAMP) = make_float2(acc[mt][nt][2], acc[mt][nt][3]);
        }
}

// ============================================================
// Kernel C: per-anchor-row loss.  <<<1024, 512>>>
// ============================================================
__global__ void __launch_bounds__(512) loss_kernel() {
    const int i = blockIdx.x;
    const int t = threadIdx.x;

    __shared__ float s_sh[N_SAMP];
    __shared__ float ep_sh[N_SAMP];
    __shared__ float en_sh[N_SAMP];
    __shared__ float warpres[16];

    const float* row = g_sim + (size_t)i * N_SAMP;
#pragma unroll
    for (int j = t; j < N_SAMP; j += 512) {
        float sv = row[j];
        s_sh[j] = sv;
        float d = sv - THRESH;
        ep_sh[j] = __expf(-SCALE_P * d);
        en_sh[j] = __expf(SCALE_N * d);
    }
    __syncthreads();

    const int w = t >> 5;       // warp = label column c
    const int lane = t & 31;
    const int c = w;

    float contrib = 0.f;
    unsigned anchorw = g_posmask[c][i >> 5];
    bool anchor = (anchorw >> (i & 31)) & 1u;

    if (anchor) {
        unsigned myword = g_posmask[c][lane];

        float minp = 1e30f, maxn = -1e30f;
#pragma unroll
        for (int it = 0; it < 32; it++) {
            unsigned m = __shfl_sync(0xffffffffu, myword, it);
            float sv = s_sh[it * 32 + lane];
            if ((m >> lane) & 1u) {
                if (sv < ONE_EPS) minp = fminf(minp, sv);
            } else {
                maxn = fmaxf(maxn, sv);
            }
        }
#pragma unroll
        for (int o = 16; o; o >>= 1) {
            minp = fminf(minp, __shfl_xor_sync(0xffffffffu, minp, o));
            maxn = fmaxf(maxn, __shfl_xor_sync(0xffffffffu, maxn, o));
        }
        float minp_eff = (minp < 1e29f) ? minp : -1e30f;

        float ps = 0.f, ns = 0.f;
        bool psel = false, nsel = false;
#pragma unroll
        for (int it = 0; it < 32; it++) {
            unsigned m = __shfl_sync(0xffffffffu, myword, it);
            int j = it * 32 + lane;
            float sv = s_sh[j];
            if ((m >> lane) & 1u) {
                if (sv < ONE_EPS && sv - MARGIN < maxn) { ps += ep_sh[j]; psel = true; }
            } else {
                if (sv + MARGIN > minp_eff) { ns += en_sh[j]; nsel = true; }
            }
        }
#pragma unroll
        for (int o = 16; o; o >>= 1) {
            ps += __shfl_xor_sync(0xffffffffu, ps, o);
            ns += __shfl_xor_sync(0xffffffffu, ns, o);
        }
        bool anyp = __any_sync(0xffffffffu, psel);
        bool anyn = __any_sync(0xffffffffu, nsel);
        if (anyp && anyn)
            contrib = log1pf(ps) / SCALE_P + log1pf(ns) / SCALE_N;
    }

    if (lane == 0) warpres[w] = contrib;
    __syncthreads();
    if (t == 0) {
        float sum = 0.f;
#pragma unroll
        for (int k = 0; k < 16; k++) sum += warpres[k];
        g_rowloss[i] = sum;
    }
}

// ============================================================
// Kernel D: final deterministic reduction.  <<<1, 256>>>
// ============================================================
__global__ void final_kernel(float* __restrict__ out) {
    int t = threadIdx.x;
    float sum = 0.f;
#pragma unroll
    for (int j = t; j < N_SAMP; j += 256) sum += g_rowloss[j];
#pragma unroll
    for (int o = 16; o; o >>= 1) sum += __shfl_xor_sync(0xffffffffu, sum, o);
    __shared__ float red[8];
    if ((t & 31) == 0) red[t >> 5] = sum;
    __syncthreads();
    if (t == 0) {
        float tot = 0.f;
#pragma unroll
        for (int k = 0; k < 8; k++) tot += red[k];
        int ta = g_total;
        out[0] = (ta > 0) ? tot / (float)ta : 0.f;
    }
}

// ============================================================
extern "C" void kernel_launch(void* const* d_in, const int* in_sizes, int n_in,
                              void* d_out, int out_size) {
    const float* feats = (const float*)d_in[0];   // (1024, 512) f32
    const int* labels  = (const int*)d_in[1];     // (1024, 16) i32
    float* out = (float*)d_out;

    static bool attr_set = false;
    if (!attr_set) {
        cudaFuncSetAttribute(mma_kernel, cudaFuncAttributeMaxDynamicSharedMemorySize,
                             SM_MMA_TOTAL);
        attr_set = true;
    }

    prep_kernel<<<1, 512>>>(labels);
    conv_kernel<<<512, 256>>>(feats);
    mma_kernel<<<dim3(8, 8), 256, SM_MMA_TOTAL>>>();
    loss_kernel<<<N_SAMP, 512>>>();
    final_kernel<<<1, 256>>>(out);
}

// round 4
// speedup vs baseline: 1.7268x; 1.1983x over previous
#include <cuda_runtime.h>
#include <cuda_bf16.h>
#include <math.h>
#include <cstdint>

#define N_SAMP 1024
#define N_FEAT 512
#define N_LAB  16

#define THRESH   0.5f
#define MARGIN   0.1f
#define SCALE_P  0.05f
#define SCALE_N  0.002f
#define ONE_EPS  0.99999f   // 1.0 - 1e-5

// ---- scratch (no allocations allowed) ----
__device__ float          g_sim[N_SAMP * N_SAMP];        // 4 MB, L2-resident
__device__ __nv_bfloat16  g_hi[N_SAMP * N_FEAT];         // 1 MB
__device__ __nv_bfloat16  g_lo[N_SAMP * N_FEAT];         // 1 MB
__device__ unsigned       g_posmask[N_LAB][N_SAMP / 32];
__device__ float          g_rowloss[N_SAMP];
__device__ int            g_done;                        // zero-init (.bss); reset in-kernel

// ============================================================
// PTX helpers (baseline ISA only: cp.async / ldmatrix / mma.sync)
// ============================================================
__device__ __forceinline__ uint32_t smem_u32(const void* p) {
    uint32_t a;
    asm("{ .reg .u64 t; cvta.to.shared.u64 t, %1; cvt.u32.u64 %0, t; }" : "=r"(a) : "l"(p));
    return a;
}
#define CP_ASYNC16(s, g) asm volatile("cp.async.cg.shared.global [%0], [%1], 16;" :: "r"(s), "l"(g) : "memory")
#define CP_COMMIT()      asm volatile("cp.async.commit_group;" ::: "memory")
#define CP_WAIT2()       asm volatile("cp.async.wait_group 2;" ::: "memory")
#define CP_WAIT1()       asm volatile("cp.async.wait_group 1;" ::: "memory")
#define CP_WAIT0()       asm volatile("cp.async.wait_group 0;" ::: "memory")

__device__ __forceinline__ void ldmatrix4(uint32_t* r, uint32_t addr) {
    asm volatile("ldmatrix.sync.aligned.m8n8.x4.shared.b16 {%0,%1,%2,%3}, [%4];"
        : "=r"(r[0]), "=r"(r[1]), "=r"(r[2]), "=r"(r[3]) : "r"(addr));
}
__device__ __forceinline__ void mma16816(float* d, const uint32_t* a, const uint32_t* b) {
    asm volatile("mma.sync.aligned.m16n8k16.row.col.f32.bf16.bf16.f32 "
        "{%0,%1,%2,%3}, {%4,%5,%6,%7}, {%8,%9}, {%0,%1,%2,%3};"
        : "+f"(d[0]), "+f"(d[1]), "+f"(d[2]), "+f"(d[3])
        : "r"(a[0]), "r"(a[1]), "r"(a[2]), "r"(a[3]), "r"(b[0]), "r"(b[1]));
}
#define SW128(off) ((off) ^ (((off) >> 3) & 0x70))

// ============================================================
// Kernel 1: conv (blocks 0..255) + prep (block 256).  512 thr.
// ============================================================
__global__ void __launch_bounds__(512) prep_conv_kernel(const float* __restrict__ F,
                                                        const int* __restrict__ labels) {
    const int b = blockIdx.x;
    const int t = threadIdx.x;

    if (b < 256) {
        // fp32 -> (bf16 hi, bf16 lo) split; 131072 float4 groups
        int gid = b * 512 + t;
        float4 v = ((const float4*)F)[gid];
        __nv_bfloat16 hx = __float2bfloat16(v.x);
        __nv_bfloat16 hy = __float2bfloat16(v.y);
        __nv_bfloat16 hz = __float2bfloat16(v.z);
        __nv_bfloat16 hw = __float2bfloat16(v.w);
        __nv_bfloat16 lx = __float2bfloat16(v.x - __bfloat162float(hx));
        __nv_bfloat16 ly = __float2bfloat16(v.y - __bfloat162float(hy));
        __nv_bfloat16 lz = __float2bfloat16(v.z - __bfloat162float(hz));
        __nv_bfloat16 lw = __float2bfloat16(v.w - __bfloat162float(hw));
        __nv_bfloat162* ho = (__nv_bfloat162*)g_hi;
        __nv_bfloat162* lo = (__nv_bfloat162*)g_lo;
        ho[gid * 2 + 0] = __nv_bfloat162(hx, hy);
        ho[gid * 2 + 1] = __nv_bfloat162(hz, hw);
        lo[gid * 2 + 0] = __nv_bfloat162(lx, ly);
        lo[gid * 2 + 1] = __nv_bfloat162(lz, lw);
    } else {
        // label bitmasks via ballot: warp w handles word groups w and w+16
        int w = t >> 5, lane = t & 31;
#pragma unroll
        for (int g = 0; g < 2; g++) {
            int wordIdx = w + g * 16;        // 0..31
            int row = wordIdx * 32 + lane;
            const int4* lp = (const int4*)(labels + row * N_LAB);
            int4 L0 = lp[0], L1 = lp[1], L2 = lp[2], L3 = lp[3];
            int lab[16] = { L0.x, L0.y, L0.z, L0.w, L1.x, L1.y, L1.z, L1.w,
                            L2.x, L2.y, L2.z, L2.w, L3.x, L3.y, L3.z, L3.w };
#pragma unroll
            for (int c = 0; c < 16; c++) {
                unsigned m = __ballot_sync(0xffffffffu, lab[c] == 1);
                if (lane == c) g_posmask[c][wordIdx] = m;
            }
        }
    }
}

// ============================================================
// Kernel 2: sim = hi@hi^T + hi@lo^T + lo@hi^T via mma.sync bf16.
// CTA tile 64x128, grid (8,16) = 128 CTAs, 8 warps (2x4),
// warp tile 32x32, K-chunk 64, 4-stage cp.async ring, SW128 smem.
// ============================================================
#define STAGE_BYTES 24576            // 8KB A (64x128B) + 16KB B (128x128B)
#define SM_MMA_TOTAL (4 * STAGE_BYTES)

__device__ __forceinline__ void issue_chunk(uint32_t sb, int tid, int bm, int bn,
                                            int chunk, int stage) {
    const int p  = chunk >> 3;
    const int kc = (chunk & 7) * 64;
    const __nv_bfloat16* Asrc = (p == 2) ? g_lo : g_hi;
    const __nv_bfloat16* Bsrc = (p == 1) ? g_lo : g_hi;
    uint32_t sA = sb + stage * STAGE_BYTES;
    uint32_t sB = sA + 8192;

    int ar = tid >> 2, ac = (tid & 3) * 16;           // A: 64 rows x 128B
    const char* gA = (const char*)(Asrc + (size_t)(bm + ar) * N_FEAT + kc);
    CP_ASYNC16(sA + SW128((uint32_t)(ar * 128 + ac)),      gA + ac);
    CP_ASYNC16(sA + SW128((uint32_t)(ar * 128 + ac + 64)), gA + ac + 64);

    int br = tid >> 1, bc = (tid & 1) * 16;           // B: 128 rows x 128B
    const char* gB = (const char*)(Bsrc + (size_t)(bn + br) * N_FEAT + kc);
#pragma unroll
    for (int j = 0; j < 4; j++)
        CP_ASYNC16(sB + SW128((uint32_t)(br * 128 + bc + j * 32)), gB + bc + j * 32);
    CP_COMMIT();
}

__global__ void __launch_bounds__(256) mma_kernel() {
    extern __shared__ char smem[];
    const uint32_t sb = smem_u32(smem);
    const int tid = threadIdx.x;
    const int bm = blockIdx.y * 64;
    const int bn = blockIdx.x * 128;
    const int wid  = tid >> 5;
    const int lane = tid & 31;
    const int wm = (wid & 1) * 32;     // warp M offset (2 rows of warps)
    const int wn = (wid >> 1) * 32;    // warp N offset (4 cols of warps)

    float acc[2][4][4];
#pragma unroll
    for (int mt = 0; mt < 2; mt++)
#pragma unroll
        for (int nt = 0; nt < 4; nt++)
#pragma unroll
            for (int q = 0; q < 4; q++) acc[mt][nt][q] = 0.f;

    issue_chunk(sb, tid, bm, bn, 0, 0);
    issue_chunk(sb, tid, bm, bn, 1, 1);
    issue_chunk(sb, tid, bm, bn, 2, 2);

    const int a_row = wm + (lane & 15);
    const int a_kb  = (lane >> 4) * 16;
    const int b_row = wn + ((lane >> 4) << 3) + (lane & 7);
    const int b_kb  = ((lane >> 3) & 1) << 4;

    for (int it = 0; it < 24; it++) {
        if (it < 22)      { CP_WAIT2(); }
        else if (it == 22){ CP_WAIT1(); }
        else              { CP_WAIT0(); }
        __syncthreads();
        if (it + 3 < 24) issue_chunk(sb, tid, bm, bn, it + 3, (it + 3) & 3);

        uint32_t aBase = sb + (it & 3) * STAGE_BYTES;
        uint32_t bBase = aBase + 8192;
#pragma unroll
        for (int kk = 0; kk < 4; kk++) {
            uint32_t a[2][4], bq[2][4];
#pragma unroll
            for (int mt = 0; mt < 2; mt++) {
                uint32_t off = SW128((uint32_t)((a_row + mt * 16) * 128 + kk * 32 + a_kb));
                ldmatrix4(a[mt], aBase + off);
            }
#pragma unroll
            for (int nt2 = 0; nt2 < 2; nt2++) {
                uint32_t off = SW128((uint32_t)((b_row + nt2 * 16) * 128 + kk * 32 + b_kb));
                ldmatrix4(bq[nt2], bBase + off);
            }
#pragma unroll
            for (int mt = 0; mt < 2; mt++)
#pragma unroll
                for (int nt = 0; nt < 4; nt++)
                    mma16816(acc[mt][nt], a[mt], &bq[nt >> 1][(nt & 1) * 2]);
        }
    }

    const int r0 = bm + wm + (lane >> 2);
    const int c0 = bn + wn + (lane & 3) * 2;
#pragma unroll
    for (int mt = 0; mt < 2; mt++)
#pragma unroll
        for (int nt = 0; nt < 4; nt++) {
            float* p0 = g_sim + (size_t)(r0 + mt * 16) * N_SAMP + c0 + nt * 8;
            *(float2*)p0 = make_float2(acc[mt][nt][0], acc[mt][nt][1]);
            *(float2*)(p0 + 8 * N_SAMP) = make_float2(acc[mt][nt][2], acc[mt][nt][3]);
        }
}

// ============================================================
// Kernel 3: per-anchor-row loss in exp-space + fused final
// reduction (last-block ticket).  <<<1024, 512>>>
// ============================================================
__global__ void __launch_bounds__(512) loss_kernel(float* __restrict__ out) {
    const int i = blockIdx.x;
    const int t = threadIdx.x;

    __shared__ float ep_sh[N_SAMP];
    __shared__ float en_sh[N_SAMP];
    __shared__ float warpres[16];
    __shared__ int   s_last;

    const float* row = g_sim + (size_t)i * N_SAMP;
#pragma unroll
    for (int j = t; j < N_SAMP; j += 512) {
        float d = row[j] - THRESH;
        ep_sh[j] = __expf(-SCALE_P * d);
        en_sh[j] = __expf(SCALE_N * d);
    }
    __syncthreads();

    const int w = t >> 5;       // warp = label column c
    const int lane = t & 31;

    float contrib = 0.f;
    bool anchor = (g_posmask[w][i >> 5] >> (i & 31)) & 1u;

    if (anchor) {
        const float EP_EPS = __expf(-SCALE_P * (ONE_EPS - THRESH));  // sv<1-eps <=> ep>EP_EPS
        const float KP     = __expf(-SCALE_P * MARGIN);
        const float KN     = __expf(-SCALE_N * MARGIN);

        unsigned myword = g_posmask[w][lane];                 // bits for j = lane*32 + b
        unsigned rotw = __funnelshift_r(myword, myword, lane); // bit b -> bit (b+lane)&31
        const int base = lane * 32;

        // ---- pass 1: en_min over filtered positives, ep_min over negatives ----
        float en_minp = 1e30f, ep_minn = 1e30f;
#pragma unroll
        for (int b = 0; b < 32; b++) {
            int idx = (b + lane) & 31;      // rotated -> conflict-free smem banks
            int j = base + idx;
            float ep = ep_sh[j];
            bool pos = (rotw >> b) & 1u;
            if (pos) {
                if (ep > EP_EPS) en_minp = fminf(en_minp, en_sh[j]);
            } else {
                ep_minn = fminf(ep_minn, ep);
            }
        }
#pragma unroll
        for (int o = 16; o; o >>= 1) {
            en_minp = fminf(en_minp, __shfl_xor_sync(0xffffffffu, en_minp, o));
            ep_minn = fminf(ep_minn, __shfl_xor_sync(0xffffffffu, ep_minn, o));
        }
        // pos_sel: ep > max(ep(max_neg)*e^{-p*M}, EP_EPS); neg_sel: en > en(min_pos)*e^{-n*M}
        float thr_p = fmaxf(ep_minn * KP, EP_EPS);
        float thr_n = (en_minp > 1e29f) ? 0.f : en_minp * KN;

        // ---- pass 2: selected exp-sums ----
        float ps = 0.f, ns = 0.f;
#pragma unroll
        for (int b = 0; b < 32; b++) {
            int idx = (b + lane) & 31;
            int j = base + idx;
            bool pos = (rotw >> b) & 1u;
            if (pos) {
                float ep = ep_sh[j];
                if (ep > thr_p) ps += ep;
            } else {
                float en = en_sh[j];
                if (en > thr_n) ns += en;
            }
        }
#pragma unroll
        for (int o = 16; o; o >>= 1) {
            ps += __shfl_xor_sync(0xffffffffu, ps, o);
            ns += __shfl_xor_sync(0xffffffffu, ns, o);
        }
        if (ps > 0.f && ns > 0.f)
            contrib = log1pf(ps) / SCALE_P + log1pf(ns) / SCALE_N;
    }

    if (lane == 0) warpres[w] = contrib;
    __syncthreads();
    if (t == 0) {
        float sum = 0.f;
#pragma unroll
        for (int k = 0; k < 16; k++) sum += warpres[k];
        g_rowloss[i] = sum;
        __threadfence();
        int ticket = atomicAdd(&g_done, 1);
        s_last = (ticket == N_SAMP - 1);
    }
    __syncthreads();

    if (s_last) {
        // last block: deterministic final reduction + anchor count
        __threadfence();
        float sum = 0.f;
#pragma unroll
        for (int j = t; j < N_SAMP; j += 512) sum += g_rowloss[j];
        int anc = __popc(g_posmask[t >> 5][t & 31]);   // 512 words exactly
#pragma unroll
        for (int o = 16; o; o >>= 1) {
            sum += __shfl_xor_sync(0xffffffffu, sum, o);
            anc += __shfl_xor_sync(0xffffffffu, anc, o);
        }
        __shared__ float redf[16];
        __shared__ int   redi[16];
        if (lane == 0) { redf[w] = sum; redi[w] = anc; }
        __syncthreads();
        if (t == 0) {
            float tot = 0.f; int ta = 0;
#pragma unroll
            for (int k = 0; k < 16; k++) { tot += redf[k]; ta += redi[k]; }
            out[0] = (ta > 0) ? tot / (float)ta : 0.f;
            g_done = 0;   // reset for graph replay determinism
        }
    }
}

// ============================================================
extern "C" void kernel_launch(void* const* d_in, const int* in_sizes, int n_in,
                              void* d_out, int out_size) {
    const float* feats = (const float*)d_in[0];   // (1024, 512) f32
    const int* labels  = (const int*)d_in[1];     // (1024, 16) i32
    float* out = (float*)d_out;

    static bool attr_set = false;
    if (!attr_set) {
        cudaFuncSetAttribute(mma_kernel, cudaFuncAttributeMaxDynamicSharedMemorySize,
                             SM_MMA_TOTAL);
        attr_set = true;
    }

    prep_conv_kernel<<<257, 512>>>(feats, labels);
    mma_kernel<<<dim3(8, 16), 256, SM_MMA_TOTAL>>>();
    loss_kernel<<<N_SAMP, 512>>>(out);
}